// round 1
// baseline (speedup 1.0000x reference)
#include <cuda_runtime.h>
#include <cstddef>

#define NN 50000
#define EE 800000
#define HEADS 4
#define HIDD 64
#define FW 256      // HEADS*HIDD
#define NEG 0.2f

// ---------------- scratch (static device globals; no allocation) ----------------
__device__ float g_feat[(size_t)NN * FW];
__device__ float g_bufA[(size_t)NN * FW];
__device__ float g_bufB[(size_t)NN * FW];
__device__ float g_el[NN * 4];
__device__ float g_er[NN * 4];
__device__ float g_feat4[NN * 8];
__device__ float g_res4[NN * 8];
__device__ float g_el4[NN * 4];
__device__ float g_er4[NN * 4];
__device__ int g_count[NN];
__device__ int g_rowstart[NN + 1];
__device__ int g_rowfill[NN];
__device__ int g_csrsrc[EE];

// ---------------- CSR build ----------------
__global__ void zero_counts_kernel() {
    int i = blockIdx.x * blockDim.x + threadIdx.x;
    if (i < NN) g_count[i] = 0;
}

__global__ void hist_kernel(const int* __restrict__ dst) {
    int i = blockIdx.x * blockDim.x + threadIdx.x;
    if (i < EE) atomicAdd(&g_count[dst[i]], 1);
}

__global__ void scan_kernel() {
    __shared__ int sh[1024];
    __shared__ int carry;
    int t = threadIdx.x;
    if (t == 0) { carry = 0; g_rowstart[0] = 0; }
    __syncthreads();
    for (int base = 0; base < NN; base += 1024) {
        int i = base + t;
        int v = (i < NN) ? g_count[i] : 0;
        sh[t] = v;
        __syncthreads();
        for (int off = 1; off < 1024; off <<= 1) {
            int u = (t >= off) ? sh[t - off] : 0;
            __syncthreads();
            sh[t] += u;
            __syncthreads();
        }
        if (i < NN) g_rowstart[i + 1] = sh[t] + carry;
        __syncthreads();
        if (t == 0) carry += sh[1023];
        __syncthreads();
    }
}

__global__ void fill_init_kernel() {
    int i = blockIdx.x * blockDim.x + threadIdx.x;
    if (i < NN) g_rowfill[i] = g_rowstart[i];
}

__global__ void scatter_kernel(const int* __restrict__ src, const int* __restrict__ dst) {
    int i = blockIdx.x * blockDim.x + threadIdx.x;
    if (i < EE) {
        int pos = atomicAdd(&g_rowfill[dst[i]], 1);
        g_csrsrc[pos] = src[i];
    }
}

// ---------------- GEMM: C[M,256] = A[M,K] * B[256,K]^T  (both K-major) ----------------
template<int K>
__global__ void __launch_bounds__(256) gemm_kernel(const float* __restrict__ A,
                                                   const float* __restrict__ B,
                                                   float* __restrict__ C, int M) {
    __shared__ float As[32][68];
    __shared__ float Bs[32][68];
    int t = threadIdx.x;
    int m0 = blockIdx.x * 64;
    int n0 = blockIdx.y * 64;
    int lrow = t >> 3;
    int lcol = (t & 7) << 2;
    int ty = t >> 4, tx = t & 15;
    int mb = ty << 2, nb = tx << 2;
    float acc[4][4];
#pragma unroll
    for (int i = 0; i < 4; i++)
#pragma unroll
        for (int j = 0; j < 4; j++) acc[i][j] = 0.f;

    for (int k0 = 0; k0 < K; k0 += 32) {
#pragma unroll
        for (int r = 0; r < 2; r++) {
            int mm = m0 + lrow + r * 32;
            float4 va = (mm < M) ? *(const float4*)(A + (size_t)mm * K + k0 + lcol)
                                 : make_float4(0.f, 0.f, 0.f, 0.f);
            As[lcol + 0][lrow + r * 32] = va.x;
            As[lcol + 1][lrow + r * 32] = va.y;
            As[lcol + 2][lrow + r * 32] = va.z;
            As[lcol + 3][lrow + r * 32] = va.w;
            int nn = n0 + lrow + r * 32;  // always < 256
            float4 vb = *(const float4*)(B + (size_t)nn * K + k0 + lcol);
            Bs[lcol + 0][lrow + r * 32] = vb.x;
            Bs[lcol + 1][lrow + r * 32] = vb.y;
            Bs[lcol + 2][lrow + r * 32] = vb.z;
            Bs[lcol + 3][lrow + r * 32] = vb.w;
        }
        __syncthreads();
#pragma unroll
        for (int k = 0; k < 32; k++) {
            float4 a = *(const float4*)(&As[k][mb]);
            float4 b = *(const float4*)(&Bs[k][nb]);
            acc[0][0] += a.x * b.x; acc[0][1] += a.x * b.y; acc[0][2] += a.x * b.z; acc[0][3] += a.x * b.w;
            acc[1][0] += a.y * b.x; acc[1][1] += a.y * b.y; acc[1][2] += a.y * b.z; acc[1][3] += a.y * b.w;
            acc[2][0] += a.z * b.x; acc[2][1] += a.z * b.y; acc[2][2] += a.z * b.z; acc[2][3] += a.z * b.w;
            acc[3][0] += a.w * b.x; acc[3][1] += a.w * b.y; acc[3][2] += a.w * b.z; acc[3][3] += a.w * b.w;
        }
        __syncthreads();
    }
#pragma unroll
    for (int i = 0; i < 4; i++) {
        int mm = m0 + mb + i;
        if (mm < M) {
            float4 o = make_float4(acc[i][0], acc[i][1], acc[i][2], acc[i][3]);
            *(float4*)(C + (size_t)mm * FW + n0 + nb) = o;
        }
    }
}

// ---------------- el/er projection (warp per node, OUT=64) ----------------
__global__ void elr_kernel(const float* __restrict__ feat, const float* __restrict__ al,
                           const float* __restrict__ ar, float* __restrict__ el,
                           float* __restrict__ er) {
    int n = (blockIdx.x * blockDim.x + threadIdx.x) >> 5;
    int lane = threadIdx.x & 31;
    if (n >= NN) return;
    const float4* f = (const float4*)(feat + (size_t)n * FW) + lane * 2;
    const float4* a4 = (const float4*)al + lane * 2;
    const float4* r4 = (const float4*)ar + lane * 2;
    float4 f0 = f[0], f1 = f[1];
    float4 a0 = a4[0], a1 = a4[1];
    float4 b0 = r4[0], b1 = r4[1];
    float pl = f0.x * a0.x + f0.y * a0.y + f0.z * a0.z + f0.w * a0.w
             + f1.x * a1.x + f1.y * a1.y + f1.z * a1.z + f1.w * a1.w;
    float pr = f0.x * b0.x + f0.y * b0.y + f0.z * b0.z + f0.w * b0.w
             + f1.x * b1.x + f1.y * b1.y + f1.z * b1.z + f1.w * b1.w;
#pragma unroll
    for (int off = 4; off >= 1; off >>= 1) {
        pl += __shfl_xor_sync(0xffffffffu, pl, off);
        pr += __shfl_xor_sync(0xffffffffu, pr, off);
    }
    if ((lane & 7) == 0) {
        el[n * 4 + (lane >> 3)] = pl;
        er[n * 4 + (lane >> 3)] = pr;
    }
}

__device__ __forceinline__ float lrelu(float x) { return x >= 0.f ? x : NEG * x; }
__device__ __forceinline__ float comp4(float4 v, int i) {
    return i == 0 ? v.x : (i == 1 ? v.y : (i == 2 ? v.z : v.w));
}

// ---------------- aggregation, OUT=64 (layers 1-3): warp per dst node ----------------
__global__ void agg64_kernel(const float* __restrict__ feat, const float* __restrict__ el,
                             const float* __restrict__ er, const float* __restrict__ resid,
                             const float* __restrict__ bias, float* __restrict__ out) {
    int n = (blockIdx.x * blockDim.x + threadIdx.x) >> 5;
    int lane = threadIdx.x & 31;
    if (n >= NN) return;
    int beg = g_rowstart[n], end = g_rowstart[n + 1];
    float4 erv = ((const float4*)er)[n];

    // pass 1: per-head max over incoming edges
    float4 m = make_float4(-1e30f, -1e30f, -1e30f, -1e30f);
    for (int i = beg + lane; i < end; i += 32) {
        int s = g_csrsrc[i];
        float4 e = ((const float4*)el)[s];
        m.x = fmaxf(m.x, lrelu(e.x + erv.x));
        m.y = fmaxf(m.y, lrelu(e.y + erv.y));
        m.z = fmaxf(m.z, lrelu(e.z + erv.z));
        m.w = fmaxf(m.w, lrelu(e.w + erv.w));
    }
#pragma unroll
    for (int off = 16; off >= 1; off >>= 1) {
        m.x = fmaxf(m.x, __shfl_xor_sync(0xffffffffu, m.x, off));
        m.y = fmaxf(m.y, __shfl_xor_sync(0xffffffffu, m.y, off));
        m.z = fmaxf(m.z, __shfl_xor_sync(0xffffffffu, m.z, off));
        m.w = fmaxf(m.w, __shfl_xor_sync(0xffffffffu, m.w, off));
    }

    // pass 2: weighted accumulation (whole warp processes one edge at a time;
    // lane owns 8 contiguous features -> h = lane>>3 is constant per lane)
    float acc[8];
#pragma unroll
    for (int k = 0; k < 8; k++) acc[k] = 0.f;
    float4 den = make_float4(0.f, 0.f, 0.f, 0.f);
    int hsel = lane >> 3;
    const float4* fb = (const float4*)feat;
    for (int i = beg; i < end; i++) {
        int s = g_csrsrc[i];
        float4 e = ((const float4*)el)[s];
        float4 ee;
        ee.x = __expf(lrelu(e.x + erv.x) - m.x);
        ee.y = __expf(lrelu(e.y + erv.y) - m.y);
        ee.z = __expf(lrelu(e.z + erv.z) - m.z);
        ee.w = __expf(lrelu(e.w + erv.w) - m.w);
        den.x += ee.x; den.y += ee.y; den.z += ee.z; den.w += ee.w;
        float w = comp4(ee, hsel);
        const float4* fr = fb + (size_t)s * (FW / 4) + lane * 2;
        float4 f0 = fr[0];
        float4 f1 = fr[1];
        acc[0] += w * f0.x; acc[1] += w * f0.y; acc[2] += w * f0.z; acc[3] += w * f0.w;
        acc[4] += w * f1.x; acc[5] += w * f1.y; acc[6] += w * f1.z; acc[7] += w * f1.w;
    }

    float dh = comp4(den, hsel);
    float inv = (end > beg) ? 1.f / dh : 0.f;
    int base = n * FW + lane * 8;
    float o[8];
#pragma unroll
    for (int k = 0; k < 8; k++) {
        float v = acc[k] * inv + bias[lane * 8 + k];
        if (resid) v += resid[base + k];
        o[k] = v > 0.f ? v : (__expf(v) - 1.f);  // ELU
    }
    *(float4*)(out + base) = make_float4(o[0], o[1], o[2], o[3]);
    *(float4*)(out + base + 4) = make_float4(o[4], o[5], o[6], o[7]);
}

// ---------------- layer 4 GEMMs: feat4 = h*W4^T, res4 = h*resW4^T (NC=8) ----------------
__global__ void __launch_bounds__(256) gemm4_kernel(const float* __restrict__ A,
                                                    const float* __restrict__ W,
                                                    const float* __restrict__ R,
                                                    float* __restrict__ F,
                                                    float* __restrict__ Rv, int M) {
    __shared__ float sW[8 * 260];
    __shared__ float sR[8 * 260];
    int t = threadIdx.x;
    for (int i = t; i < 2048; i += 256) {
        int j = i >> 8, k = i & 255;
        sW[j * 260 + k] = W[i];
        sR[j * 260 + k] = R[i];
    }
    __syncthreads();
    int nl = t >> 3, j = t & 7;
    int n = blockIdx.x * 32 + nl;
    if (n >= M) return;
    const float4* a = (const float4*)(A + (size_t)n * 256);
    const float4* w = (const float4*)(sW + j * 260);
    const float4* r = (const float4*)(sR + j * 260);
    float s1 = 0.f, s2 = 0.f;
#pragma unroll 8
    for (int k = 0; k < 64; k++) {
        float4 av = a[k];
        float4 wv = w[k];
        float4 rv = r[k];
        s1 += av.x * wv.x + av.y * wv.y + av.z * wv.z + av.w * wv.w;
        s2 += av.x * rv.x + av.y * rv.y + av.z * rv.z + av.w * rv.w;
    }
    F[(size_t)n * 8 + j] = s1;
    Rv[(size_t)n * 8 + j] = s2;
}

__global__ void elr4_kernel(const float* __restrict__ feat4, const float* __restrict__ al4,
                            const float* __restrict__ ar4, float* __restrict__ el4,
                            float* __restrict__ er4) {
    int n = blockIdx.x * blockDim.x + threadIdx.x;
    if (n >= NN) return;
    float4 f0 = ((const float4*)feat4)[n * 2];
    float4 f1 = ((const float4*)feat4)[n * 2 + 1];
    float4 a0 = ((const float4*)al4)[0], a1 = ((const float4*)al4)[1];
    float4 r0 = ((const float4*)ar4)[0], r1 = ((const float4*)ar4)[1];
    float4 el, er;
    el.x = f0.x * a0.x + f0.y * a0.y;  er.x = f0.x * r0.x + f0.y * r0.y;
    el.y = f0.z * a0.z + f0.w * a0.w;  er.y = f0.z * r0.z + f0.w * r0.w;
    el.z = f1.x * a1.x + f1.y * a1.y;  er.z = f1.x * r1.x + f1.y * r1.y;
    el.w = f1.z * a1.z + f1.w * a1.w;  er.w = f1.z * r1.z + f1.w * r1.w;
    ((float4*)el4)[n] = el;
    ((float4*)er4)[n] = er;
}

// ---------------- layer 4 aggregation + softmax + head-mean ----------------
__global__ void agg4_kernel(const float* __restrict__ feat4, const float* __restrict__ el4,
                            const float* __restrict__ er4, const float* __restrict__ res4,
                            const float* __restrict__ b4, float* __restrict__ out) {
    int n = (blockIdx.x * blockDim.x + threadIdx.x) >> 5;
    int lane = threadIdx.x & 31;
    if (n >= NN) return;
    int beg = g_rowstart[n], end = g_rowstart[n + 1];
    float4 erv = ((const float4*)er4)[n];

    float4 m = make_float4(-1e30f, -1e30f, -1e30f, -1e30f);
    for (int i = beg + lane; i < end; i += 32) {
        int s = g_csrsrc[i];
        float4 e = ((const float4*)el4)[s];
        m.x = fmaxf(m.x, lrelu(e.x + erv.x));
        m.y = fmaxf(m.y, lrelu(e.y + erv.y));
        m.z = fmaxf(m.z, lrelu(e.z + erv.z));
        m.w = fmaxf(m.w, lrelu(e.w + erv.w));
    }
#pragma unroll
    for (int off = 16; off >= 1; off >>= 1) {
        m.x = fmaxf(m.x, __shfl_xor_sync(0xffffffffu, m.x, off));
        m.y = fmaxf(m.y, __shfl_xor_sync(0xffffffffu, m.y, off));
        m.z = fmaxf(m.z, __shfl_xor_sync(0xffffffffu, m.z, off));
        m.w = fmaxf(m.w, __shfl_xor_sync(0xffffffffu, m.w, off));
    }

    float acc = 0.f;
    float4 den = make_float4(0.f, 0.f, 0.f, 0.f);
    int h = (lane >> 1) & 3;  // lane<8: lane = h*2 + c
    for (int i = beg; i < end; i++) {
        int s = g_csrsrc[i];
        float4 e = ((const float4*)el4)[s];
        float4 ee;
        ee.x = __expf(lrelu(e.x + erv.x) - m.x);
        ee.y = __expf(lrelu(e.y + erv.y) - m.y);
        ee.z = __expf(lrelu(e.z + erv.z) - m.z);
        ee.w = __expf(lrelu(e.w + erv.w) - m.w);
        den.x += ee.x; den.y += ee.y; den.z += ee.z; den.w += ee.w;
        if (lane < 8) acc += comp4(ee, h) * feat4[(size_t)s * 8 + lane];
    }

    float v = 0.f;
    if (lane < 8) {
        float dh = comp4(den, h);
        v = (end > beg ? acc / dh : 0.f) + res4[n * 8 + lane] + b4[lane];
    }
    // softmax over the class pair (lane, lane^1), then mean over 4 heads
    float other = __shfl_xor_sync(0xffffffffu, v, 1);
    float mx = fmaxf(v, other);
    float ev = __expf(v - mx);
    float eo = __expf(other - mx);
    float sm = ev / (ev + eo);
    sm += __shfl_xor_sync(0xffffffffu, sm, 4);
    sm += __shfl_xor_sync(0xffffffffu, sm, 2);
    if (lane < 2) out[n * 2 + lane] = sm * 0.25f;
}

// ---------------- host ----------------
extern "C" void kernel_launch(void* const* d_in, const int* in_sizes, int n_in,
                              void* d_out, int out_size) {
    const float* x    = (const float*)d_in[0];
    const int*   src  = (const int*)d_in[1];
    const int*   dst  = (const int*)d_in[2];
    const float* W1   = (const float*)d_in[3];
    const float* al1  = (const float*)d_in[4];
    const float* ar1  = (const float*)d_in[5];
    const float* b1   = (const float*)d_in[6];
    const float* W2   = (const float*)d_in[7];
    const float* al2  = (const float*)d_in[8];
    const float* ar2  = (const float*)d_in[9];
    const float* b2   = (const float*)d_in[10];
    const float* W3   = (const float*)d_in[11];
    const float* al3  = (const float*)d_in[12];
    const float* ar3  = (const float*)d_in[13];
    const float* b3   = (const float*)d_in[14];
    const float* W4   = (const float*)d_in[15];
    const float* al4  = (const float*)d_in[16];
    const float* ar4  = (const float*)d_in[17];
    const float* b4   = (const float*)d_in[18];
    const float* rW4  = (const float*)d_in[19];
    float* out = (float*)d_out;

    void *p_feat, *p_bufA, *p_bufB, *p_el, *p_er, *p_f4, *p_r4, *p_el4, *p_er4;
    cudaGetSymbolAddress(&p_feat, g_feat);
    cudaGetSymbolAddress(&p_bufA, g_bufA);
    cudaGetSymbolAddress(&p_bufB, g_bufB);
    cudaGetSymbolAddress(&p_el, g_el);
    cudaGetSymbolAddress(&p_er, g_er);
    cudaGetSymbolAddress(&p_f4, g_feat4);
    cudaGetSymbolAddress(&p_r4, g_res4);
    cudaGetSymbolAddress(&p_el4, g_el4);
    cudaGetSymbolAddress(&p_er4, g_er4);
    float* feat = (float*)p_feat;
    float* bufA = (float*)p_bufA;
    float* bufB = (float*)p_bufB;
    float* el   = (float*)p_el;
    float* er   = (float*)p_er;
    float* f4   = (float*)p_f4;
    float* r4   = (float*)p_r4;
    float* el4  = (float*)p_el4;
    float* er4  = (float*)p_er4;

    const int TB = 256;
    int nodeBlocks = (NN + TB - 1) / TB;
    int edgeBlocks = (EE + TB - 1) / TB;
    int warpBlocks = (NN * 32 + TB - 1) / TB;  // warp-per-node kernels
    dim3 gemmGrid((NN + 63) / 64, 4);

    // --- CSR build (reused by all layers) ---
    zero_counts_kernel<<<nodeBlocks, TB>>>();
    hist_kernel<<<edgeBlocks, TB>>>(dst);
    scan_kernel<<<1, 1024>>>();
    fill_init_kernel<<<nodeBlocks, TB>>>();
    scatter_kernel<<<edgeBlocks, TB>>>(src, dst);

    // --- layer 1: IN=128 -> 256, no residual ---
    gemm_kernel<128><<<gemmGrid, TB>>>(x, W1, feat, NN);
    elr_kernel<<<warpBlocks, TB>>>(feat, al1, ar1, el, er);
    agg64_kernel<<<warpBlocks, TB>>>(feat, el, er, nullptr, b1, bufA);

    // --- layer 2: 256 -> 256, identity residual ---
    gemm_kernel<256><<<gemmGrid, TB>>>(bufA, W2, feat, NN);
    elr_kernel<<<warpBlocks, TB>>>(feat, al2, ar2, el, er);
    agg64_kernel<<<warpBlocks, TB>>>(feat, el, er, bufA, b2, bufB);

    // --- layer 3: 256 -> 256, identity residual ---
    gemm_kernel<256><<<gemmGrid, TB>>>(bufB, W3, feat, NN);
    elr_kernel<<<warpBlocks, TB>>>(feat, al3, ar3, el, er);
    agg64_kernel<<<warpBlocks, TB>>>(feat, el, er, bufB, b3, bufA);

    // --- layer 4: 256 -> 8, fc residual, softmax + head-mean ---
    gemm4_kernel<<<(NN + 31) / 32, TB>>>(bufA, W4, rW4, f4, r4, NN);
    elr4_kernel<<<nodeBlocks, TB>>>(f4, al4, ar4, el4, er4);
    agg4_kernel<<<warpBlocks, TB>>>(f4, el4, er4, r4, b4, out);
}

// round 2
// speedup vs baseline: 1.4195x; 1.4195x over previous
#include <cuda_runtime.h>
#include <cstddef>
#include <cstdint>

#define NN 50000
#define EE 800000
#define HEADS 4
#define HIDD 64
#define FW 256      // HEADS*HIDD
#define NEG 0.2f

// ---------------- scratch (static device globals; no allocation) ----------------
__device__ float g_feat[(size_t)NN * FW];
__device__ float g_bufA[(size_t)NN * FW];
__device__ float g_bufB[(size_t)NN * FW];
__device__ float g_el[NN * 4];
__device__ float g_er[NN * 4];
__device__ float g_feat4[NN * 8];
__device__ float g_res4[NN * 8];
__device__ float g_el4[NN * 4];
__device__ float g_er4[NN * 4];
__device__ int g_count[NN];
__device__ int g_rowstart[NN + 1];
__device__ int g_rowfill[NN];
__device__ int g_csrsrc[EE];

// ---------------- CSR build ----------------
__global__ void zero_counts_kernel() {
    int i = blockIdx.x * blockDim.x + threadIdx.x;
    if (i < NN) g_count[i] = 0;
}

__global__ void hist_kernel(const int* __restrict__ dst) {
    int i = blockIdx.x * blockDim.x + threadIdx.x;
    if (i < EE) atomicAdd(&g_count[dst[i]], 1);
}

__global__ void scan_kernel() {
    __shared__ int sh[1024];
    __shared__ int carry;
    int t = threadIdx.x;
    if (t == 0) { carry = 0; g_rowstart[0] = 0; }
    __syncthreads();
    for (int base = 0; base < NN; base += 1024) {
        int i = base + t;
        int v = (i < NN) ? g_count[i] : 0;
        sh[t] = v;
        __syncthreads();
        for (int off = 1; off < 1024; off <<= 1) {
            int u = (t >= off) ? sh[t - off] : 0;
            __syncthreads();
            sh[t] += u;
            __syncthreads();
        }
        if (i < NN) g_rowstart[i + 1] = sh[t] + carry;
        __syncthreads();
        if (t == 0) carry += sh[1023];
        __syncthreads();
    }
}

__global__ void fill_init_kernel() {
    int i = blockIdx.x * blockDim.x + threadIdx.x;
    if (i < NN) g_rowfill[i] = g_rowstart[i];
}

__global__ void scatter_kernel(const int* __restrict__ src, const int* __restrict__ dst) {
    int i = blockIdx.x * blockDim.x + threadIdx.x;
    if (i < EE) {
        int pos = atomicAdd(&g_rowfill[dst[i]], 1);
        g_csrsrc[pos] = src[i];
    }
}

// ---------------- tf32 tensor-core GEMM: C[M,256] = A[M,K] * B[256,K]^T ----------------
// CTA tile 128x128, 8 warps (4 in M x 2 in N), warp tile 32x64,
// mma.sync.m16n8k8 tf32, k-tile 32. Smem stride 36 floats -> all fragment
// LDS.32 are conflict-free (bank = 4*group + tid_in_group, a bijection).
template<int K>
__global__ void __launch_bounds__(256, 2) gemm_tc_kernel(const float* __restrict__ A,
                                                         const float* __restrict__ B,
                                                         float* __restrict__ C, int M) {
    __shared__ float As[128][36];
    __shared__ float Bs[128][36];
    int t = threadIdx.x;
    int lane = t & 31;
    int warp = t >> 5;
    int wm = warp & 3;          // 0..3  (M direction)
    int wn = warp >> 2;         // 0..1  (N direction)
    int g = lane >> 2;          // groupID 0..7
    int tg = lane & 3;          // tid-in-group 0..3
    int m0 = blockIdx.x * 128;
    int n0 = blockIdx.y * 128;

    float c[2][8][4];
#pragma unroll
    for (int mf = 0; mf < 2; mf++)
#pragma unroll
        for (int nf = 0; nf < 8; nf++)
#pragma unroll
            for (int k = 0; k < 4; k++) c[mf][nf][k] = 0.f;

    for (int kt = 0; kt < K; kt += 32) {
        // global -> smem (with tf32 rounding): 128 rows x 8 float4 each tile
#pragma unroll
        for (int j = 0; j < 4; j++) {
            int idx = t + j * 256;
            int row = idx >> 3;
            int kq = idx & 7;
            const float* gp = A + (size_t)(m0 + row) * K + kt + kq * 4;
            float4 v = (m0 + row < M) ? *(const float4*)gp : make_float4(0.f, 0.f, 0.f, 0.f);
            uint4 u;
            asm("cvt.rna.tf32.f32 %0, %1;" : "=r"(u.x) : "f"(v.x));
            asm("cvt.rna.tf32.f32 %0, %1;" : "=r"(u.y) : "f"(v.y));
            asm("cvt.rna.tf32.f32 %0, %1;" : "=r"(u.z) : "f"(v.z));
            asm("cvt.rna.tf32.f32 %0, %1;" : "=r"(u.w) : "f"(v.w));
            *(uint4*)&As[row][kq * 4] = u;
            const float* gq = B + (size_t)(n0 + row) * K + kt + kq * 4;  // n0+row < 256 always
            float4 w = *(const float4*)gq;
            uint4 uw;
            asm("cvt.rna.tf32.f32 %0, %1;" : "=r"(uw.x) : "f"(w.x));
            asm("cvt.rna.tf32.f32 %0, %1;" : "=r"(uw.y) : "f"(w.y));
            asm("cvt.rna.tf32.f32 %0, %1;" : "=r"(uw.z) : "f"(w.z));
            asm("cvt.rna.tf32.f32 %0, %1;" : "=r"(uw.w) : "f"(w.w));
            *(uint4*)&Bs[row][kq * 4] = uw;
        }
        __syncthreads();

#pragma unroll
        for (int ks = 0; ks < 32; ks += 8) {
            uint32_t a[2][4], b[8][2];
#pragma unroll
            for (int mf = 0; mf < 2; mf++) {
                int r = wm * 32 + mf * 16 + g;
                a[mf][0] = __float_as_uint(As[r][ks + tg]);
                a[mf][1] = __float_as_uint(As[r + 8][ks + tg]);
                a[mf][2] = __float_as_uint(As[r][ks + tg + 4]);
                a[mf][3] = __float_as_uint(As[r + 8][ks + tg + 4]);
            }
#pragma unroll
            for (int nf = 0; nf < 8; nf++) {
                int col = wn * 64 + nf * 8 + g;
                b[nf][0] = __float_as_uint(Bs[col][ks + tg]);
                b[nf][1] = __float_as_uint(Bs[col][ks + tg + 4]);
            }
#pragma unroll
            for (int mf = 0; mf < 2; mf++)
#pragma unroll
                for (int nf = 0; nf < 8; nf++) {
                    asm volatile(
                        "mma.sync.aligned.m16n8k8.row.col.f32.tf32.tf32.f32 "
                        "{%0,%1,%2,%3}, {%4,%5,%6,%7}, {%8,%9}, {%0,%1,%2,%3};"
                        : "+f"(c[mf][nf][0]), "+f"(c[mf][nf][1]),
                          "+f"(c[mf][nf][2]), "+f"(c[mf][nf][3])
                        : "r"(a[mf][0]), "r"(a[mf][1]), "r"(a[mf][2]), "r"(a[mf][3]),
                          "r"(b[nf][0]), "r"(b[nf][1]));
                }
        }
        __syncthreads();
    }

    // epilogue: c0/c1 -> row g, c2/c3 -> row g+8; cols tg*2, tg*2+1
#pragma unroll
    for (int mf = 0; mf < 2; mf++) {
        int r0 = m0 + wm * 32 + mf * 16 + g;
#pragma unroll
        for (int nf = 0; nf < 8; nf++) {
            int col = n0 + wn * 64 + nf * 8 + tg * 2;
            if (r0 < M)
                *(float2*)(C + (size_t)r0 * FW + col) = make_float2(c[mf][nf][0], c[mf][nf][1]);
            if (r0 + 8 < M)
                *(float2*)(C + (size_t)(r0 + 8) * FW + col) = make_float2(c[mf][nf][2], c[mf][nf][3]);
        }
    }
}

// ---------------- el/er projection (warp per node, OUT=64) ----------------
__global__ void elr_kernel(const float* __restrict__ feat, const float* __restrict__ al,
                           const float* __restrict__ ar, float* __restrict__ el,
                           float* __restrict__ er) {
    int n = (blockIdx.x * blockDim.x + threadIdx.x) >> 5;
    int lane = threadIdx.x & 31;
    if (n >= NN) return;
    const float4* f = (const float4*)(feat + (size_t)n * FW) + lane * 2;
    const float4* a4 = (const float4*)al + lane * 2;
    const float4* r4 = (const float4*)ar + lane * 2;
    float4 f0 = f[0], f1 = f[1];
    float4 a0 = a4[0], a1 = a4[1];
    float4 b0 = r4[0], b1 = r4[1];
    float pl = f0.x * a0.x + f0.y * a0.y + f0.z * a0.z + f0.w * a0.w
             + f1.x * a1.x + f1.y * a1.y + f1.z * a1.z + f1.w * a1.w;
    float pr = f0.x * b0.x + f0.y * b0.y + f0.z * b0.z + f0.w * b0.w
             + f1.x * b1.x + f1.y * b1.y + f1.z * b1.z + f1.w * b1.w;
#pragma unroll
    for (int off = 4; off >= 1; off >>= 1) {
        pl += __shfl_xor_sync(0xffffffffu, pl, off);
        pr += __shfl_xor_sync(0xffffffffu, pr, off);
    }
    if ((lane & 7) == 0) {
        el[n * 4 + (lane >> 3)] = pl;
        er[n * 4 + (lane >> 3)] = pr;
    }
}

__device__ __forceinline__ float lrelu(float x) { return x >= 0.f ? x : NEG * x; }
__device__ __forceinline__ float comp4(float4 v, int i) {
    return i == 0 ? v.x : (i == 1 ? v.y : (i == 2 ? v.z : v.w));
}

// ---------------- aggregation, OUT=64 (layers 1-3): warp per dst node ----------------
__global__ void agg64_kernel(const float* __restrict__ feat, const float* __restrict__ el,
                             const float* __restrict__ er, const float* __restrict__ resid,
                             const float* __restrict__ bias, float* __restrict__ out) {
    int n = (blockIdx.x * blockDim.x + threadIdx.x) >> 5;
    int lane = threadIdx.x & 31;
    if (n >= NN) return;
    int beg = g_rowstart[n], end = g_rowstart[n + 1];
    float4 erv = ((const float4*)er)[n];

    // pass 1: per-head max over incoming edges
    float4 m = make_float4(-1e30f, -1e30f, -1e30f, -1e30f);
    for (int i = beg + lane; i < end; i += 32) {
        int s = g_csrsrc[i];
        float4 e = ((const float4*)el)[s];
        m.x = fmaxf(m.x, lrelu(e.x + erv.x));
        m.y = fmaxf(m.y, lrelu(e.y + erv.y));
        m.z = fmaxf(m.z, lrelu(e.z + erv.z));
        m.w = fmaxf(m.w, lrelu(e.w + erv.w));
    }
#pragma unroll
    for (int off = 16; off >= 1; off >>= 1) {
        m.x = fmaxf(m.x, __shfl_xor_sync(0xffffffffu, m.x, off));
        m.y = fmaxf(m.y, __shfl_xor_sync(0xffffffffu, m.y, off));
        m.z = fmaxf(m.z, __shfl_xor_sync(0xffffffffu, m.z, off));
        m.w = fmaxf(m.w, __shfl_xor_sync(0xffffffffu, m.w, off));
    }

    // pass 2: weighted accumulation
    float acc[8];
#pragma unroll
    for (int k = 0; k < 8; k++) acc[k] = 0.f;
    float4 den = make_float4(0.f, 0.f, 0.f, 0.f);
    int hsel = lane >> 3;
    const float4* fb = (const float4*)feat;
    for (int i = beg; i < end; i++) {
        int s = g_csrsrc[i];
        float4 e = ((const float4*)el)[s];
        float4 ee;
        ee.x = __expf(lrelu(e.x + erv.x) - m.x);
        ee.y = __expf(lrelu(e.y + erv.y) - m.y);
        ee.z = __expf(lrelu(e.z + erv.z) - m.z);
        ee.w = __expf(lrelu(e.w + erv.w) - m.w);
        den.x += ee.x; den.y += ee.y; den.z += ee.z; den.w += ee.w;
        float w = comp4(ee, hsel);
        const float4* fr = fb + (size_t)s * (FW / 4) + lane * 2;
        float4 f0 = fr[0];
        float4 f1 = fr[1];
        acc[0] += w * f0.x; acc[1] += w * f0.y; acc[2] += w * f0.z; acc[3] += w * f0.w;
        acc[4] += w * f1.x; acc[5] += w * f1.y; acc[6] += w * f1.z; acc[7] += w * f1.w;
    }

    float dh = comp4(den, hsel);
    float inv = (end > beg) ? 1.f / dh : 0.f;
    int base = n * FW + lane * 8;
    float o[8];
#pragma unroll
    for (int k = 0; k < 8; k++) {
        float v = acc[k] * inv + bias[lane * 8 + k];
        if (resid) v += resid[base + k];
        o[k] = v > 0.f ? v : (__expf(v) - 1.f);  // ELU
    }
    *(float4*)(out + base) = make_float4(o[0], o[1], o[2], o[3]);
    *(float4*)(out + base + 4) = make_float4(o[4], o[5], o[6], o[7]);
}

// ---------------- layer 4 GEMMs: feat4 = h*W4^T, res4 = h*resW4^T (NC=8) ----------------
__global__ void __launch_bounds__(256) gemm4_kernel(const float* __restrict__ A,
                                                    const float* __restrict__ W,
                                                    const float* __restrict__ R,
                                                    float* __restrict__ F,
                                                    float* __restrict__ Rv, int M) {
    __shared__ float sW[8 * 260];
    __shared__ float sR[8 * 260];
    int t = threadIdx.x;
    for (int i = t; i < 2048; i += 256) {
        int j = i >> 8, k = i & 255;
        sW[j * 260 + k] = W[i];
        sR[j * 260 + k] = R[i];
    }
    __syncthreads();
    int nl = t >> 3, j = t & 7;
    int n = blockIdx.x * 32 + nl;
    if (n >= M) return;
    const float4* a = (const float4*)(A + (size_t)n * 256);
    const float4* w = (const float4*)(sW + j * 260);
    const float4* r = (const float4*)(sR + j * 260);
    float s1 = 0.f, s2 = 0.f;
#pragma unroll 8
    for (int k = 0; k < 64; k++) {
        float4 av = a[k];
        float4 wv = w[k];
        float4 rv = r[k];
        s1 += av.x * wv.x + av.y * wv.y + av.z * wv.z + av.w * wv.w;
        s2 += av.x * rv.x + av.y * rv.y + av.z * rv.z + av.w * rv.w;
    }
    F[(size_t)n * 8 + j] = s1;
    Rv[(size_t)n * 8 + j] = s2;
}

__global__ void elr4_kernel(const float* __restrict__ feat4, const float* __restrict__ al4,
                            const float* __restrict__ ar4, float* __restrict__ el4,
                            float* __restrict__ er4) {
    int n = blockIdx.x * blockDim.x + threadIdx.x;
    if (n >= NN) return;
    float4 f0 = ((const float4*)feat4)[n * 2];
    float4 f1 = ((const float4*)feat4)[n * 2 + 1];
    float4 a0 = ((const float4*)al4)[0], a1 = ((const float4*)al4)[1];
    float4 r0 = ((const float4*)ar4)[0], r1 = ((const float4*)ar4)[1];
    float4 el, er;
    el.x = f0.x * a0.x + f0.y * a0.y;  er.x = f0.x * r0.x + f0.y * r0.y;
    el.y = f0.z * a0.z + f0.w * a0.w;  er.y = f0.z * r0.z + f0.w * r0.w;
    el.z = f1.x * a1.x + f1.y * a1.y;  er.z = f1.x * r1.x + f1.y * r1.y;
    el.w = f1.z * a1.z + f1.w * a1.w;  er.w = f1.z * r1.z + f1.w * r1.w;
    ((float4*)el4)[n] = el;
    ((float4*)er4)[n] = er;
}

// ---------------- layer 4 aggregation + softmax + head-mean ----------------
__global__ void agg4_kernel(const float* __restrict__ feat4, const float* __restrict__ el4,
                            const float* __restrict__ er4, const float* __restrict__ res4,
                            const float* __restrict__ b4, float* __restrict__ out) {
    int n = (blockIdx.x * blockDim.x + threadIdx.x) >> 5;
    int lane = threadIdx.x & 31;
    if (n >= NN) return;
    int beg = g_rowstart[n], end = g_rowstart[n + 1];
    float4 erv = ((const float4*)er4)[n];

    float4 m = make_float4(-1e30f, -1e30f, -1e30f, -1e30f);
    for (int i = beg + lane; i < end; i += 32) {
        int s = g_csrsrc[i];
        float4 e = ((const float4*)el4)[s];
        m.x = fmaxf(m.x, lrelu(e.x + erv.x));
        m.y = fmaxf(m.y, lrelu(e.y + erv.y));
        m.z = fmaxf(m.z, lrelu(e.z + erv.z));
        m.w = fmaxf(m.w, lrelu(e.w + erv.w));
    }
#pragma unroll
    for (int off = 16; off >= 1; off >>= 1) {
        m.x = fmaxf(m.x, __shfl_xor_sync(0xffffffffu, m.x, off));
        m.y = fmaxf(m.y, __shfl_xor_sync(0xffffffffu, m.y, off));
        m.z = fmaxf(m.z, __shfl_xor_sync(0xffffffffu, m.z, off));
        m.w = fmaxf(m.w, __shfl_xor_sync(0xffffffffu, m.w, off));
    }

    float acc = 0.f;
    float4 den = make_float4(0.f, 0.f, 0.f, 0.f);
    int h = (lane >> 1) & 3;  // lane<8: lane = h*2 + c
    for (int i = beg; i < end; i++) {
        int s = g_csrsrc[i];
        float4 e = ((const float4*)el4)[s];
        float4 ee;
        ee.x = __expf(lrelu(e.x + erv.x) - m.x);
        ee.y = __expf(lrelu(e.y + erv.y) - m.y);
        ee.z = __expf(lrelu(e.z + erv.z) - m.z);
        ee.w = __expf(lrelu(e.w + erv.w) - m.w);
        den.x += ee.x; den.y += ee.y; den.z += ee.z; den.w += ee.w;
        if (lane < 8) acc += comp4(ee, h) * feat4[(size_t)s * 8 + lane];
    }

    float v = 0.f;
    if (lane < 8) {
        float dh = comp4(den, h);
        v = (end > beg ? acc / dh : 0.f) + res4[n * 8 + lane] + b4[lane];
    }
    float other = __shfl_xor_sync(0xffffffffu, v, 1);
    float mx = fmaxf(v, other);
    float ev = __expf(v - mx);
    float eo = __expf(other - mx);
    float sm = ev / (ev + eo);
    sm += __shfl_xor_sync(0xffffffffu, sm, 4);
    sm += __shfl_xor_sync(0xffffffffu, sm, 2);
    if (lane < 2) out[n * 2 + lane] = sm * 0.25f;
}

// ---------------- host ----------------
extern "C" void kernel_launch(void* const* d_in, const int* in_sizes, int n_in,
                              void* d_out, int out_size) {
    const float* x    = (const float*)d_in[0];
    const int*   src  = (const int*)d_in[1];
    const int*   dst  = (const int*)d_in[2];
    const float* W1   = (const float*)d_in[3];
    const float* al1  = (const float*)d_in[4];
    const float* ar1  = (const float*)d_in[5];
    const float* b1   = (const float*)d_in[6];
    const float* W2   = (const float*)d_in[7];
    const float* al2  = (const float*)d_in[8];
    const float* ar2  = (const float*)d_in[9];
    const float* b2   = (const float*)d_in[10];
    const float* W3   = (const float*)d_in[11];
    const float* al3  = (const float*)d_in[12];
    const float* ar3  = (const float*)d_in[13];
    const float* b3   = (const float*)d_in[14];
    const float* W4   = (const float*)d_in[15];
    const float* al4  = (const float*)d_in[16];
    const float* ar4  = (const float*)d_in[17];
    const float* b4   = (const float*)d_in[18];
    const float* rW4  = (const float*)d_in[19];
    float* out = (float*)d_out;

    void *p_feat, *p_bufA, *p_bufB, *p_el, *p_er, *p_f4, *p_r4, *p_el4, *p_er4;
    cudaGetSymbolAddress(&p_feat, g_feat);
    cudaGetSymbolAddress(&p_bufA, g_bufA);
    cudaGetSymbolAddress(&p_bufB, g_bufB);
    cudaGetSymbolAddress(&p_el, g_el);
    cudaGetSymbolAddress(&p_er, g_er);
    cudaGetSymbolAddress(&p_f4, g_feat4);
    cudaGetSymbolAddress(&p_r4, g_res4);
    cudaGetSymbolAddress(&p_el4, g_el4);
    cudaGetSymbolAddress(&p_er4, g_er4);
    float* feat = (float*)p_feat;
    float* bufA = (float*)p_bufA;
    float* bufB = (float*)p_bufB;
    float* el   = (float*)p_el;
    float* er   = (float*)p_er;
    float* f4   = (float*)p_f4;
    float* r4   = (float*)p_r4;
    float* el4  = (float*)p_el4;
    float* er4  = (float*)p_er4;

    const int TB = 256;
    int nodeBlocks = (NN + TB - 1) / TB;
    int edgeBlocks = (EE + TB - 1) / TB;
    int warpBlocks = (NN * 32 + TB - 1) / TB;  // warp-per-node kernels
    dim3 gemmGrid((NN + 127) / 128, 2);

    // --- CSR build (reused by all layers) ---
    zero_counts_kernel<<<nodeBlocks, TB>>>();
    hist_kernel<<<edgeBlocks, TB>>>(dst);
    scan_kernel<<<1, 1024>>>();
    fill_init_kernel<<<nodeBlocks, TB>>>();
    scatter_kernel<<<edgeBlocks, TB>>>(src, dst);

    // --- layer 1: IN=128 -> 256, no residual ---
    gemm_tc_kernel<128><<<gemmGrid, TB>>>(x, W1, feat, NN);
    elr_kernel<<<warpBlocks, TB>>>(feat, al1, ar1, el, er);
    agg64_kernel<<<warpBlocks, TB>>>(feat, el, er, nullptr, b1, bufA);

    // --- layer 2: 256 -> 256, identity residual ---
    gemm_tc_kernel<256><<<gemmGrid, TB>>>(bufA, W2, feat, NN);
    elr_kernel<<<warpBlocks, TB>>>(feat, al2, ar2, el, er);
    agg64_kernel<<<warpBlocks, TB>>>(feat, el, er, bufA, b2, bufB);

    // --- layer 3: 256 -> 256, identity residual ---
    gemm_tc_kernel<256><<<gemmGrid, TB>>>(bufB, W3, feat, NN);
    elr_kernel<<<warpBlocks, TB>>>(feat, al3, ar3, el, er);
    agg64_kernel<<<warpBlocks, TB>>>(feat, el, er, bufB, b3, bufA);

    // --- layer 4: 256 -> 8, fc residual, softmax + head-mean ---
    gemm4_kernel<<<(NN + 31) / 32, TB>>>(bufA, W4, rW4, f4, r4, NN);
    elr4_kernel<<<nodeBlocks, TB>>>(f4, al4, ar4, el4, er4);
    agg4_kernel<<<warpBlocks, TB>>>(f4, el4, er4, r4, b4, out);
}

// round 4
// speedup vs baseline: 1.7103x; 1.2049x over previous
#include <cuda_runtime.h>
#include <cuda_fp16.h>
#include <cstddef>
#include <cstdint>

#define NN 50000
#define EE 800000
#define HEADS 4
#define HIDD 64
#define FW 256      // HEADS*HIDD
#define NEG 0.2f

// ---------------- scratch (static device globals; no allocation) ----------------
__device__ float g_feat[(size_t)NN * FW];
__device__ __half2 g_featH[(size_t)NN * (FW / 2)];
__device__ float g_bufA[(size_t)NN * FW];
__device__ float g_bufB[(size_t)NN * FW];
__device__ float g_el[NN * 4];
__device__ float g_er[NN * 4];
__device__ float g_feat4[NN * 8];
__device__ float g_res4[NN * 8];
__device__ float g_el4[NN * 4];
__device__ float g_er4[NN * 4];
__device__ int g_count[NN];
__device__ int g_rowstart[NN + 1];
__device__ int g_rowfill[NN];
__device__ int g_csrsrc[EE];

// ---------------- CSR build ----------------
__global__ void zero_counts_kernel() {
    int i = blockIdx.x * blockDim.x + threadIdx.x;
    if (i < NN) g_count[i] = 0;
}

__global__ void hist_kernel(const int* __restrict__ dst) {
    int i = blockIdx.x * blockDim.x + threadIdx.x;
    if (i < EE) atomicAdd(&g_count[dst[i]], 1);
}

__global__ void scan_kernel() {
    __shared__ int sh[1024];
    __shared__ int carry;
    int t = threadIdx.x;
    if (t == 0) { carry = 0; g_rowstart[0] = 0; }
    __syncthreads();
    for (int base = 0; base < NN; base += 1024) {
        int i = base + t;
        int v = (i < NN) ? g_count[i] : 0;
        sh[t] = v;
        __syncthreads();
        for (int off = 1; off < 1024; off <<= 1) {
            int u = (t >= off) ? sh[t - off] : 0;
            __syncthreads();
            sh[t] += u;
            __syncthreads();
        }
        if (i < NN) {
            int incl = sh[t] + carry;
            g_rowstart[i + 1] = incl;
            g_rowfill[i] = incl - v;   // exclusive prefix = rowstart[i]
        }
        __syncthreads();
        if (t == 0) carry += sh[1023];
        __syncthreads();
    }
}

__global__ void scatter_kernel(const int* __restrict__ src, const int* __restrict__ dst) {
    int i = blockIdx.x * blockDim.x + threadIdx.x;
    if (i < EE) {
        int pos = atomicAdd(&g_rowfill[dst[i]], 1);
        g_csrsrc[pos] = src[i];
    }
}

// ---------------- tf32 tensor-core GEMM: C[M,256] = A[M,K] * B[256,K]^T ----------------
// Also emits an fp16 copy (CH) of C for the gather path.
template<int K>
__global__ void __launch_bounds__(256, 2) gemm_tc_kernel(const float* __restrict__ A,
                                                         const float* __restrict__ B,
                                                         float* __restrict__ C,
                                                         __half2* __restrict__ CH, int M) {
    __shared__ float As[128][36];
    __shared__ float Bs[128][36];
    int t = threadIdx.x;
    int lane = t & 31;
    int warp = t >> 5;
    int wm = warp & 3;          // 0..3  (M direction)
    int wn = warp >> 2;         // 0..1  (N direction)
    int g = lane >> 2;          // groupID 0..7
    int tg = lane & 3;          // tid-in-group 0..3
    int m0 = blockIdx.x * 128;
    int n0 = blockIdx.y * 128;

    float c[2][8][4];
#pragma unroll
    for (int mf = 0; mf < 2; mf++)
#pragma unroll
        for (int nf = 0; nf < 8; nf++)
#pragma unroll
            for (int k = 0; k < 4; k++) c[mf][nf][k] = 0.f;

    for (int kt = 0; kt < K; kt += 32) {
#pragma unroll
        for (int j = 0; j < 4; j++) {
            int idx = t + j * 256;
            int row = idx >> 3;
            int kq = idx & 7;
            const float* gp = A + (size_t)(m0 + row) * K + kt + kq * 4;
            float4 v = (m0 + row < M) ? *(const float4*)gp : make_float4(0.f, 0.f, 0.f, 0.f);
            uint4 u;
            asm("cvt.rna.tf32.f32 %0, %1;" : "=r"(u.x) : "f"(v.x));
            asm("cvt.rna.tf32.f32 %0, %1;" : "=r"(u.y) : "f"(v.y));
            asm("cvt.rna.tf32.f32 %0, %1;" : "=r"(u.z) : "f"(v.z));
            asm("cvt.rna.tf32.f32 %0, %1;" : "=r"(u.w) : "f"(v.w));
            *(uint4*)&As[row][kq * 4] = u;
            const float* gq = B + (size_t)(n0 + row) * K + kt + kq * 4;  // n0+row < 256 always
            float4 w = *(const float4*)gq;
            uint4 uw;
            asm("cvt.rna.tf32.f32 %0, %1;" : "=r"(uw.x) : "f"(w.x));
            asm("cvt.rna.tf32.f32 %0, %1;" : "=r"(uw.y) : "f"(w.y));
            asm("cvt.rna.tf32.f32 %0, %1;" : "=r"(uw.z) : "f"(w.z));
            asm("cvt.rna.tf32.f32 %0, %1;" : "=r"(uw.w) : "f"(w.w));
            *(uint4*)&Bs[row][kq * 4] = uw;
        }
        __syncthreads();

#pragma unroll
        for (int ks = 0; ks < 32; ks += 8) {
            uint32_t a[2][4], b[8][2];
#pragma unroll
            for (int mf = 0; mf < 2; mf++) {
                int r = wm * 32 + mf * 16 + g;
                a[mf][0] = __float_as_uint(As[r][ks + tg]);
                a[mf][1] = __float_as_uint(As[r + 8][ks + tg]);
                a[mf][2] = __float_as_uint(As[r][ks + tg + 4]);
                a[mf][3] = __float_as_uint(As[r + 8][ks + tg + 4]);
            }
#pragma unroll
            for (int nf = 0; nf < 8; nf++) {
                int col = wn * 64 + nf * 8 + g;
                b[nf][0] = __float_as_uint(Bs[col][ks + tg]);
                b[nf][1] = __float_as_uint(Bs[col][ks + tg + 4]);
            }
#pragma unroll
            for (int mf = 0; mf < 2; mf++)
#pragma unroll
                for (int nf = 0; nf < 8; nf++) {
                    asm volatile(
                        "mma.sync.aligned.m16n8k8.row.col.f32.tf32.tf32.f32 "
                        "{%0,%1,%2,%3}, {%4,%5,%6,%7}, {%8,%9}, {%0,%1,%2,%3};"
                        : "+f"(c[mf][nf][0]), "+f"(c[mf][nf][1]),
                          "+f"(c[mf][nf][2]), "+f"(c[mf][nf][3])
                        : "r"(a[mf][0]), "r"(a[mf][1]), "r"(a[mf][2]), "r"(a[mf][3]),
                          "r"(b[nf][0]), "r"(b[nf][1]));
                }
        }
        __syncthreads();
    }

#pragma unroll
    for (int mf = 0; mf < 2; mf++) {
        int r0 = m0 + wm * 32 + mf * 16 + g;
#pragma unroll
        for (int nf = 0; nf < 8; nf++) {
            int col = n0 + wn * 64 + nf * 8 + tg * 2;
            if (r0 < M) {
                *(float2*)(C + (size_t)r0 * FW + col) = make_float2(c[mf][nf][0], c[mf][nf][1]);
                CH[(size_t)r0 * (FW / 2) + (col >> 1)] = __floats2half2_rn(c[mf][nf][0], c[mf][nf][1]);
            }
            if (r0 + 8 < M) {
                *(float2*)(C + (size_t)(r0 + 8) * FW + col) = make_float2(c[mf][nf][2], c[mf][nf][3]);
                CH[(size_t)(r0 + 8) * (FW / 2) + (col >> 1)] = __floats2half2_rn(c[mf][nf][2], c[mf][nf][3]);
            }
        }
    }
}

// ---------------- el/er projection (warp per node, OUT=64) ----------------
__global__ void elr_kernel(const float* __restrict__ feat, const float* __restrict__ al,
                           const float* __restrict__ ar, float* __restrict__ el,
                           float* __restrict__ er) {
    int n = (blockIdx.x * blockDim.x + threadIdx.x) >> 5;
    int lane = threadIdx.x & 31;
    if (n >= NN) return;
    const float4* f = (const float4*)(feat + (size_t)n * FW) + lane * 2;
    const float4* a4 = (const float4*)al + lane * 2;
    const float4* r4 = (const float4*)ar + lane * 2;
    float4 f0 = f[0], f1 = f[1];
    float4 a0 = a4[0], a1 = a4[1];
    float4 b0 = r4[0], b1 = r4[1];
    float pl = f0.x * a0.x + f0.y * a0.y + f0.z * a0.z + f0.w * a0.w
             + f1.x * a1.x + f1.y * a1.y + f1.z * a1.z + f1.w * a1.w;
    float pr = f0.x * b0.x + f0.y * b0.y + f0.z * b0.z + f0.w * b0.w
             + f1.x * b1.x + f1.y * b1.y + f1.z * b1.z + f1.w * b1.w;
#pragma unroll
    for (int off = 4; off >= 1; off >>= 1) {
        pl += __shfl_xor_sync(0xffffffffu, pl, off);
        pr += __shfl_xor_sync(0xffffffffu, pr, off);
    }
    if ((lane & 7) == 0) {
        el[n * 4 + (lane >> 3)] = pl;
        er[n * 4 + (lane >> 3)] = pr;
    }
}

__device__ __forceinline__ float lrelu(float x) { return x >= 0.f ? x : NEG * x; }
__device__ __forceinline__ float comp4(float4 v, int i) {
    return i == 0 ? v.x : (i == 1 ? v.y : (i == 2 ? v.z : v.w));
}

// ---------------- aggregation, OUT=64 (layers 1-3): warp per dst node ----------------
// Chunked: weights computed edge-parallel per 32-edge chunk, stashed in smem;
// serial loop only does the fp16 feature gather + FFMA.
__global__ void __launch_bounds__(256) agg64_kernel(const __half2* __restrict__ featH,
                                                    const float* __restrict__ el,
                                                    const float* __restrict__ er,
                                                    const float* __restrict__ resid,
                                                    const float* __restrict__ bias,
                                                    float* __restrict__ out) {
    __shared__ float4 s_ee[8][32];
    __shared__ int s_src[8][32];
    int warp = threadIdx.x >> 5;
    int n = (blockIdx.x * blockDim.x + threadIdx.x) >> 5;
    int lane = threadIdx.x & 31;
    if (n >= NN) return;
    int beg = g_rowstart[n], end = g_rowstart[n + 1];
    float4 erv = ((const float4*)er)[n];

    // pass 1: per-head max over incoming edges
    float4 m = make_float4(-1e30f, -1e30f, -1e30f, -1e30f);
    for (int i = beg + lane; i < end; i += 32) {
        int s = g_csrsrc[i];
        float4 e = ((const float4*)el)[s];
        m.x = fmaxf(m.x, lrelu(e.x + erv.x));
        m.y = fmaxf(m.y, lrelu(e.y + erv.y));
        m.z = fmaxf(m.z, lrelu(e.z + erv.z));
        m.w = fmaxf(m.w, lrelu(e.w + erv.w));
    }
#pragma unroll
    for (int off = 16; off >= 1; off >>= 1) {
        m.x = fmaxf(m.x, __shfl_xor_sync(0xffffffffu, m.x, off));
        m.y = fmaxf(m.y, __shfl_xor_sync(0xffffffffu, m.y, off));
        m.z = fmaxf(m.z, __shfl_xor_sync(0xffffffffu, m.z, off));
        m.w = fmaxf(m.w, __shfl_xor_sync(0xffffffffu, m.w, off));
    }

    float acc[8];
#pragma unroll
    for (int k = 0; k < 8; k++) acc[k] = 0.f;
    float4 den = make_float4(0.f, 0.f, 0.f, 0.f);
    int hsel = lane >> 3;

    for (int c = beg; c < end; c += 32) {
        // phase a: edge-parallel weight computation
        int i = c + lane;
        float4 ee = make_float4(0.f, 0.f, 0.f, 0.f);
        int s = 0;
        if (i < end) {
            s = g_csrsrc[i];
            float4 e = ((const float4*)el)[s];
            ee.x = __expf(lrelu(e.x + erv.x) - m.x);
            ee.y = __expf(lrelu(e.y + erv.y) - m.y);
            ee.z = __expf(lrelu(e.z + erv.z) - m.z);
            ee.w = __expf(lrelu(e.w + erv.w) - m.w);
            den.x += ee.x; den.y += ee.y; den.z += ee.z; den.w += ee.w;
        }
        s_ee[warp][lane] = ee;
        s_src[warp][lane] = s;
        __syncwarp();
        // phase b: serial gather + accumulate
        int cnt = min(end - c, 32);
        const float* wsm = (const float*)&s_ee[warp][0];
        for (int j = 0; j < cnt; j++) {
            int sj = s_src[warp][j];
            float w = wsm[j * 4 + hsel];
            float4 hv = *(const float4*)(featH + (size_t)sj * (FW / 2) + lane * 4);
            float2 f0 = __half22float2(((const __half2*)&hv)[0]);
            float2 f1 = __half22float2(((const __half2*)&hv)[1]);
            float2 f2 = __half22float2(((const __half2*)&hv)[2]);
            float2 f3 = __half22float2(((const __half2*)&hv)[3]);
            acc[0] += w * f0.x; acc[1] += w * f0.y;
            acc[2] += w * f1.x; acc[3] += w * f1.y;
            acc[4] += w * f2.x; acc[5] += w * f2.y;
            acc[6] += w * f3.x; acc[7] += w * f3.y;
        }
        __syncwarp();
    }

    // warp-reduce denominators
#pragma unroll
    for (int off = 16; off >= 1; off >>= 1) {
        den.x += __shfl_xor_sync(0xffffffffu, den.x, off);
        den.y += __shfl_xor_sync(0xffffffffu, den.y, off);
        den.z += __shfl_xor_sync(0xffffffffu, den.z, off);
        den.w += __shfl_xor_sync(0xffffffffu, den.w, off);
    }
    float dh = comp4(den, hsel);
    float inv = (end > beg) ? 1.f / dh : 0.f;
    int base = n * FW + lane * 8;
    float o[8];
#pragma unroll
    for (int k = 0; k < 8; k++) {
        float v = acc[k] * inv + bias[lane * 8 + k];
        if (resid) v += resid[base + k];
        o[k] = v > 0.f ? v : (__expf(v) - 1.f);  // ELU
    }
    *(float4*)(out + base) = make_float4(o[0], o[1], o[2], o[3]);
    *(float4*)(out + base + 4) = make_float4(o[4], o[5], o[6], o[7]);
}

// ---------------- layer 4 GEMMs: feat4 = h*W4^T, res4 = h*resW4^T (NC=8) ----------------
__global__ void __launch_bounds__(256) gemm4_kernel(const float* __restrict__ A,
                                                    const float* __restrict__ W,
                                                    const float* __restrict__ R,
                                                    float* __restrict__ F,
                                                    float* __restrict__ Rv, int M) {
    __shared__ float sW[8 * 260];
    __shared__ float sR[8 * 260];
    int t = threadIdx.x;
    for (int i = t; i < 2048; i += 256) {
        int j = i >> 8, k = i & 255;
        sW[j * 260 + k] = W[i];
        sR[j * 260 + k] = R[i];
    }
    __syncthreads();
    int nl = t >> 3, j = t & 7;
    int n = blockIdx.x * 32 + nl;
    if (n >= M) return;
    const float4* a = (const float4*)(A + (size_t)n * 256);
    const float4* w = (const float4*)(sW + j * 260);
    const float4* r = (const float4*)(sR + j * 260);
    float s1 = 0.f, s2 = 0.f;
#pragma unroll 8
    for (int k = 0; k < 64; k++) {
        float4 av = a[k];
        float4 wv = w[k];
        float4 rv = r[k];
        s1 += av.x * wv.x + av.y * wv.y + av.z * wv.z + av.w * wv.w;
        s2 += av.x * rv.x + av.y * rv.y + av.z * rv.z + av.w * rv.w;
    }
    F[(size_t)n * 8 + j] = s1;
    Rv[(size_t)n * 8 + j] = s2;
}

__global__ void elr4_kernel(const float* __restrict__ feat4, const float* __restrict__ al4,
                            const float* __restrict__ ar4, float* __restrict__ el4,
                            float* __restrict__ er4) {
    int n = blockIdx.x * blockDim.x + threadIdx.x;
    if (n >= NN) return;
    float4 f0 = ((const float4*)feat4)[n * 2];
    float4 f1 = ((const float4*)feat4)[n * 2 + 1];
    float4 a0 = ((const float4*)al4)[0], a1 = ((const float4*)al4)[1];
    float4 r0 = ((const float4*)ar4)[0], r1 = ((const float4*)ar4)[1];
    float4 el, er;
    el.x = f0.x * a0.x + f0.y * a0.y;  er.x = f0.x * r0.x + f0.y * r0.y;
    el.y = f0.z * a0.z + f0.w * a0.w;  er.y = f0.z * r0.z + f0.w * r0.w;
    el.z = f1.x * a1.x + f1.y * a1.y;  er.z = f1.x * r1.x + f1.y * r1.y;
    el.w = f1.z * a1.z + f1.w * a1.w;  er.w = f1.z * r1.z + f1.w * r1.w;
    ((float4*)el4)[n] = el;
    ((float4*)er4)[n] = er;
}

// ---------------- layer 4 aggregation + softmax + head-mean ----------------
__global__ void agg4_kernel(const float* __restrict__ feat4, const float* __restrict__ el4,
                            const float* __restrict__ er4, const float* __restrict__ res4,
                            const float* __restrict__ b4, float* __restrict__ out) {
    int n = (blockIdx.x * blockDim.x + threadIdx.x) >> 5;
    int lane = threadIdx.x & 31;
    if (n >= NN) return;
    int beg = g_rowstart[n], end = g_rowstart[n + 1];
    float4 erv = ((const float4*)er4)[n];

    float4 m = make_float4(-1e30f, -1e30f, -1e30f, -1e30f);
    for (int i = beg + lane; i < end; i += 32) {
        int s = g_csrsrc[i];
        float4 e = ((const float4*)el4)[s];
        m.x = fmaxf(m.x, lrelu(e.x + erv.x));
        m.y = fmaxf(m.y, lrelu(e.y + erv.y));
        m.z = fmaxf(m.z, lrelu(e.z + erv.z));
        m.w = fmaxf(m.w, lrelu(e.w + erv.w));
    }
#pragma unroll
    for (int off = 16; off >= 1; off >>= 1) {
        m.x = fmaxf(m.x, __shfl_xor_sync(0xffffffffu, m.x, off));
        m.y = fmaxf(m.y, __shfl_xor_sync(0xffffffffu, m.y, off));
        m.z = fmaxf(m.z, __shfl_xor_sync(0xffffffffu, m.z, off));
        m.w = fmaxf(m.w, __shfl_xor_sync(0xffffffffu, m.w, off));
    }

    float acc = 0.f;
    float4 den = make_float4(0.f, 0.f, 0.f, 0.f);
    int h = (lane >> 1) & 3;  // lane<8: lane = h*2 + c
    for (int i = beg; i < end; i++) {
        int s = g_csrsrc[i];
        float4 e = ((const float4*)el4)[s];
        float4 ee;
        ee.x = __expf(lrelu(e.x + erv.x) - m.x);
        ee.y = __expf(lrelu(e.y + erv.y) - m.y);
        ee.z = __expf(lrelu(e.z + erv.z) - m.z);
        ee.w = __expf(lrelu(e.w + erv.w) - m.w);
        den.x += ee.x; den.y += ee.y; den.z += ee.z; den.w += ee.w;
        if (lane < 8) acc += comp4(ee, h) * feat4[(size_t)s * 8 + lane];
    }

    float v = 0.f;
    if (lane < 8) {
        float dh = comp4(den, h);
        v = (end > beg ? acc / dh : 0.f) + res4[n * 8 + lane] + b4[lane];
    }
    float other = __shfl_xor_sync(0xffffffffu, v, 1);
    float mx = fmaxf(v, other);
    float ev = __expf(v - mx);
    float eo = __expf(other - mx);
    float sm = ev / (ev + eo);
    sm += __shfl_xor_sync(0xffffffffu, sm, 4);
    sm += __shfl_xor_sync(0xffffffffu, sm, 2);
    if (lane < 2) out[n * 2 + lane] = sm * 0.25f;
}

// ---------------- host ----------------
extern "C" void kernel_launch(void* const* d_in, const int* in_sizes, int n_in,
                              void* d_out, int out_size) {
    const float* x    = (const float*)d_in[0];
    const int*   src  = (const int*)d_in[1];
    const int*   dst  = (const int*)d_in[2];
    const float* W1   = (const float*)d_in[3];
    const float* al1  = (const float*)d_in[4];
    const float* ar1  = (const float*)d_in[5];
    const float* b1   = (const float*)d_in[6];
    const float* W2   = (const float*)d_in[7];
    const float* al2  = (const float*)d_in[8];
    const float* ar2  = (const float*)d_in[9];
    const float* b2   = (const float*)d_in[10];
    const float* W3   = (const float*)d_in[11];
    const float* al3  = (const float*)d_in[12];
    const float* ar3  = (const float*)d_in[13];
    const float* b3   = (const float*)d_in[14];
    const float* W4   = (const float*)d_in[15];
    const float* al4  = (const float*)d_in[16];
    const float* ar4  = (const float*)d_in[17];
    const float* b4   = (const float*)d_in[18];
    const float* rW4  = (const float*)d_in[19];
    float* out = (float*)d_out;

    void *p_feat, *p_featH, *p_bufA, *p_bufB, *p_el, *p_er, *p_f4, *p_r4, *p_el4, *p_er4;
    cudaGetSymbolAddress(&p_feat, g_feat);
    cudaGetSymbolAddress(&p_featH, g_featH);
    cudaGetSymbolAddress(&p_bufA, g_bufA);
    cudaGetSymbolAddress(&p_bufB, g_bufB);
    cudaGetSymbolAddress(&p_el, g_el);
    cudaGetSymbolAddress(&p_er, g_er);
    cudaGetSymbolAddress(&p_f4, g_feat4);
    cudaGetSymbolAddress(&p_r4, g_res4);
    cudaGetSymbolAddress(&p_el4, g_el4);
    cudaGetSymbolAddress(&p_er4, g_er4);
    float* feat = (float*)p_feat;
    __half2* featH = (__half2*)p_featH;
    float* bufA = (float*)p_bufA;
    float* bufB = (float*)p_bufB;
    float* el   = (float*)p_el;
    float* er   = (float*)p_er;
    float* f4   = (float*)p_f4;
    float* r4   = (float*)p_r4;
    float* el4  = (float*)p_el4;
    float* er4  = (float*)p_er4;

    const int TB = 256;
    int nodeBlocks = (NN + TB - 1) / TB;
    int edgeBlocks = (EE + TB - 1) / TB;
    int warpBlocks = (NN * 32 + TB - 1) / TB;  // warp-per-node kernels
    dim3 gemmGrid((NN + 127) / 128, 2);

    // --- CSR build (reused by all layers) ---
    zero_counts_kernel<<<nodeBlocks, TB>>>();
    hist_kernel<<<edgeBlocks, TB>>>(dst);
    scan_kernel<<<1, 1024>>>();
    scatter_kernel<<<edgeBlocks, TB>>>(src, dst);

    // --- layer 1: IN=128 -> 256, no residual ---
    gemm_tc_kernel<128><<<gemmGrid, TB>>>(x, W1, feat, featH, NN);
    elr_kernel<<<warpBlocks, TB>>>(feat, al1, ar1, el, er);
    agg64_kernel<<<warpBlocks, TB>>>(featH, el, er, nullptr, b1, bufA);

    // --- layer 2: 256 -> 256, identity residual ---
    gemm_tc_kernel<256><<<gemmGrid, TB>>>(bufA, W2, feat, featH, NN);
    elr_kernel<<<warpBlocks, TB>>>(feat, al2, ar2, el, er);
    agg64_kernel<<<warpBlocks, TB>>>(featH, el, er, bufA, b2, bufB);

    // --- layer 3: 256 -> 256, identity residual ---
    gemm_tc_kernel<256><<<gemmGrid, TB>>>(bufB, W3, feat, featH, NN);
    elr_kernel<<<warpBlocks, TB>>>(feat, al3, ar3, el, er);
    agg64_kernel<<<warpBlocks, TB>>>(featH, el, er, bufB, b3, bufA);

    // --- layer 4: 256 -> 8, fc residual, softmax + head-mean ---
    gemm4_kernel<<<(NN + 31) / 32, TB>>>(bufA, W4, rW4, f4, r4, NN);
    elr4_kernel<<<nodeBlocks, TB>>>(f4, al4, ar4, el4, er4);
    agg4_kernel<<<warpBlocks, TB>>>(f4, el4, er4, r4, b4, out);
}